// round 3
// baseline (speedup 1.0000x reference)
#include <cuda_runtime.h>
#include <math.h>

// Problem dims
#define Bn   4
#define Tn   1024
#define Fn   500
#define Hn   128
#define Pn   64
#define G3   384          // 3*H
#define CTXW 16384        // 2*H*P
#define STP  1088         // padded time stride (64 left pad + 1024)
#define PADOFF 64

// Scratch (__device__ globals: no allocation allowed)
__device__ float g_gi[Bn*Tn*G3];            // 6.3 MB
__device__ float g_states_bt[Bn*Tn*Hn];     // 2 MB   [b*T+t, h]
__device__ float g_states_pad[Bn*Hn*STP];   // 2.2 MB [b, h, 64+t] (pad 1..63 = s0)
__device__ float g_W1r[Hn*Hn];
__device__ float g_gated[Bn*Tn*Hn];         // 2 MB
__device__ float g_states_fallback[Tn*Bn*Hn];

// ---------------- W1r precompute: W1r[o,h] = sum_p W_ctx[o, h*P+p] ----------
__global__ void k_w1r(const float* __restrict__ Wctx) {
    int o = blockIdx.x, h = threadIdx.x;
    const float* src = Wctx + (size_t)o * CTXW + h * Pn;
    float s = 0.f;
    #pragma unroll
    for (int p = 0; p < Pn; p++) s += src[p];
    g_W1r[o * Hn + h] = s;
}

// ---------------- Stage 1: gi = x @ W_ih^T  (4096 x 384 x 500) --------------
#define BM 64
#define BN 64
#define BK 16
__global__ void k_gemm_gi(const float* __restrict__ A, const float* __restrict__ W) {
    __shared__ float As[BK][BM + 1];
    __shared__ float Ws[BK][BN + 1];
    int m0 = blockIdx.y * BM, n0 = blockIdx.x * BN;
    int tid = threadIdx.x;
    int tx = tid & 15, ty = tid >> 4;
    float acc[4][4] = {};
    for (int k0 = 0; k0 < Fn; k0 += BK) {
        #pragma unroll
        for (int i = 0; i < 4; i++) {
            int e = tid + i * 256;
            int r = e >> 4, c = e & 15;
            int kk = k0 + c;
            As[c][r] = (kk < Fn) ? A[(size_t)(m0 + r) * Fn + kk] : 0.f;
        }
        #pragma unroll
        for (int i = 0; i < 4; i++) {
            int e = tid + i * 256;
            int r = e >> 4, c = e & 15;
            int kk = k0 + c;
            Ws[c][r] = (kk < Fn) ? W[(size_t)(n0 + r) * Fn + kk] : 0.f;
        }
        __syncthreads();
        #pragma unroll
        for (int k = 0; k < BK; k++) {
            float a[4], w[4];
            #pragma unroll
            for (int i = 0; i < 4; i++) a[i] = As[k][ty * 4 + i];
            #pragma unroll
            for (int j = 0; j < 4; j++) w[j] = Ws[k][tx * 4 + j];
            #pragma unroll
            for (int i = 0; i < 4; i++)
                #pragma unroll
                for (int j = 0; j < 4; j++)
                    acc[i][j] += a[i] * w[j];
        }
        __syncthreads();
    }
    #pragma unroll
    for (int i = 0; i < 4; i++)
        #pragma unroll
        for (int j = 0; j < 4; j++)
            g_gi[(size_t)(m0 + ty * 4 + i) * G3 + n0 + tx * 4 + j] = acc[i][j];
}

// ---------------- Stage 1b: gates -> states (3 layouts) ---------------------
// out_states == nullptr -> write all_states to the device-global fallback.
__global__ void k_gates(const float* __restrict__ b_ih, const float* __restrict__ b_hh,
                        float* out_states) {
    int bt = blockIdx.x, h = threadIdx.x;
    int b = bt >> 10, t = bt & 1023;
    float* dst = out_states ? out_states : g_states_fallback;
    const float* gi = g_gi + (size_t)bt * G3;
    float r = 1.f / (1.f + expf(-(gi[h]        + b_ih[h]        + b_hh[h])));
    float z = 1.f / (1.f + expf(-(gi[Hn + h]   + b_ih[Hn + h]   + b_hh[Hn + h])));
    float n = tanhf(gi[2 * Hn + h] + b_ih[2 * Hn + h] + r * b_hh[2 * Hn + h]);
    float s = (1.f - z) * n;
    dst[((size_t)t * Bn + b) * Hn + h] = s;                 // all_states [T,B,H]
    g_states_bt[(size_t)bt * Hn + h] = s;
    float* pad = g_states_pad + ((size_t)b * Hn + h) * STP;
    pad[PADOFF + t] = s;
    if (t == 0) {
        for (int j = 1; j < PADOFF; j++) pad[j] = s;        // clip -> replicate s0
    }
}

// ---------------- Stage 2: context gate (conv-GEMM + W1r term) --------------
// CTA tile: 64 timesteps x 64 outputs. grid = (2 n-split, 16 t-tiles, 4 batch)
__global__ void k_ctx(const float* __restrict__ Wctx, const float* __restrict__ b_ctx) {
    __shared__ float ws[64][68];   // [p][o_local], padded rows (16B aligned)
    __shared__ float v[128];       // states_pad window for current h
    __shared__ float wr[64];       // W1r column
    int o0 = blockIdx.x * 64, t0 = blockIdx.y * 64, b = blockIdx.z;
    int tid = threadIdx.x, tx = tid & 15, ty = tid >> 4;
    float acc[4][4] = {};

    for (int h = 0; h < Hn; h++) {
        const float* wsrc = Wctx + (size_t)(Hn + h) * Pn + (size_t)o0 * CTXW;
        #pragma unroll
        for (int i = 0; i < 16; i++) {
            int e = tid + i * 256;
            int ol = e >> 6, p = e & 63;
            ws[p][ol] = wsrc[(size_t)ol * CTXW + p];
        }
        if (tid < 127)
            v[tid] = g_states_pad[((size_t)b * Hn + h) * STP + t0 + 1 + tid];
        if (tid >= 128 && tid < 192)
            wr[tid - 128] = g_W1r[(o0 + tid - 128) * Hn + h];
        __syncthreads();

        // part1: acc += W1r[o,h] * s[t,h]   (s[t,h] == v[63+tl])
        {
            float wv[4], va[4];
            #pragma unroll
            for (int j = 0; j < 4; j++) wv[j] = wr[tx * 4 + j];
            #pragma unroll
            for (int i = 0; i < 4; i++) va[i] = v[63 + ty * 4 + i];
            #pragma unroll
            for (int i = 0; i < 4; i++)
                #pragma unroll
                for (int j = 0; j < 4; j++) acc[i][j] += va[i] * wv[j];
        }
        // conv: acc[tl][ol] += sum_p v[63+tl-p] * ws[p][ol]
        // register sliding window on v: 1 new LDS per p
        float va[4];
        #pragma unroll
        for (int i = 0; i < 4; i++) va[i] = v[63 + ty * 4 + i];
        #pragma unroll
        for (int p = 0; p < 64; p++) {
            float4 wv = *(const float4*)&ws[p][tx * 4];
            #pragma unroll
            for (int i = 0; i < 4; i++) {
                acc[i][0] += va[i] * wv.x;
                acc[i][1] += va[i] * wv.y;
                acc[i][2] += va[i] * wv.z;
                acc[i][3] += va[i] * wv.w;
            }
            if (p < 63) {
                va[3] = va[2]; va[2] = va[1]; va[1] = va[0];
                va[0] = v[62 + ty * 4 - p];
            }
        }
        __syncthreads();
    }

    // epilogue: gate = sigmoid(acc + b_ctx); gated = state * gate
    #pragma unroll
    for (int i = 0; i < 4; i++) {
        int t = t0 + ty * 4 + i;
        #pragma unroll
        for (int j = 0; j < 4; j++) {
            int o = o0 + tx * 4 + j;
            float y = acc[i][j] + b_ctx[o];
            float gate = 1.f / (1.f + expf(-y));
            float s = g_states_bt[((size_t)b * Tn + t) * Hn + o];
            g_gated[((size_t)b * Tn + t) * Hn + o] = s * gate;
        }
    }
}

// ---------------- Stage 3: probs = clip(sigmoid(gated @ W_fc^T + b_fc)) -----
__global__ void k_probs(const float* __restrict__ Wfc, const float* __restrict__ b_fc,
                        float* __restrict__ probs) {
    __shared__ float gs[64][33];
    __shared__ float wf[64][33];
    int r0 = blockIdx.x * 64;
    int tid = threadIdx.x, tx = tid & 15, ty = tid >> 4;
    float acc[4][4] = {};
    for (int k0 = 0; k0 < Hn; k0 += 32) {
        #pragma unroll
        for (int i = 0; i < 8; i++) {
            int e = tid + i * 256;
            int r = e >> 5, c = e & 31;
            gs[r][c] = g_gated[(size_t)(r0 + r) * Hn + k0 + c];
            wf[r][c] = Wfc[(size_t)r * Hn + k0 + c];
        }
        __syncthreads();
        #pragma unroll
        for (int k = 0; k < 32; k++) {
            float a[4], w[4];
            #pragma unroll
            for (int i = 0; i < 4; i++) a[i] = gs[ty * 4 + i][k];
            #pragma unroll
            for (int j = 0; j < 4; j++) w[j] = wf[tx * 4 + j][k];
            #pragma unroll
            for (int i = 0; i < 4; i++)
                #pragma unroll
                for (int j = 0; j < 4; j++) acc[i][j] += a[i] * w[j];
        }
        __syncthreads();
    }
    #pragma unroll
    for (int i = 0; i < 4; i++) {
        int row = r0 + ty * 4 + i;
        #pragma unroll
        for (int j = 0; j < 4; j++) {
            int p = tx * 4 + j;
            float y = acc[i][j] + b_fc[p];
            float pr = 1.f / (1.f + expf(-y));
            pr = fminf(fmaxf(pr, 0.001f), 0.999f);
            probs[(size_t)row * Pn + p] = pr;
        }
    }
}

// ---------------- launch -----------------------------------------------------
extern "C" void kernel_launch(void* const* d_in, const int* in_sizes, int n_in,
                              void* d_out, int out_size) {
    const float* x     = (const float*)d_in[0];
    const float* W_ih  = (const float*)d_in[1];
    // d_in[2] = W_hh (unused: hidden state is always zero in the reference)
    const float* b_ih  = (const float*)d_in[3];
    const float* b_hh  = (const float*)d_in[4];
    const float* W_ctx = (const float*)d_in[5];
    const float* b_ctx = (const float*)d_in[6];
    const float* W_fc  = (const float*)d_in[7];
    const float* b_fc  = (const float*)d_in[8];

    float* out = (float*)d_out;
    const int PROBS_N = Bn * Tn * Pn;            // 262144
    const int TOTAL_N = PROBS_N + Tn * Bn * Hn;  // 786432
    float* out_probs  = out;
    // tuple order: (probs, all_states); if out only holds probs, states go to
    // the device-global fallback (selected inside k_gates, no host API needed)
    float* out_states = (out_size >= TOTAL_N) ? (out + PROBS_N) : nullptr;

    k_w1r<<<Hn, Hn>>>(W_ctx);
    k_gemm_gi<<<dim3(G3 / BN, (Bn * Tn) / BM), 256>>>(x, W_ih);
    k_gates<<<Bn * Tn, Hn>>>(b_ih, b_hh, out_states);
    k_ctx<<<dim3(2, Tn / 64, Bn), 256>>>(W_ctx, b_ctx);
    k_probs<<<(Bn * Tn) / 64, 256>>>(W_fc, b_fc, out_probs);
}

// round 7
// speedup vs baseline: 2.1510x; 2.1510x over previous
#include <cuda_runtime.h>
#include <cuda_bf16.h>
#include <math.h>
#include <stdint.h>

// Problem dims
#define Bn   4
#define Tn   1024
#define Fn   500
#define Hn   128
#define Pn   64
#define G3   384          // 3*H
#define CTXW 16384        // 2*H*P
#define STP  1088         // padded time rows (64 left pad + 1024)
#define PADOFF 64

// Scratch (__device__ globals: no allocation allowed)
__device__ float g_gi[Bn*Tn*G3];                 // 6.3 MB
__device__ float g_states_bt[Bn*Tn*Hn];          // 2 MB   [b*T+t, h] fp32 exact
__device__ __nv_bfloat16 g_Apad[Bn*STP*Hn];      // 1.1 MB [b][64+t][h] bf16 (rows 1..63 = s0)
__device__ float g_W1r[Hn*Hn];
__device__ float g_gated[Bn*Tn*Hn];              // 2 MB
__device__ __nv_bfloat16 g_Bw[64*128*128];       // 2 MB: [p][o][h] bf16, W1r folded at p=0
__device__ float g_states_fallback[Tn*Bn*Hn];

// ---------------- helpers ----------------------------------------------------
__device__ __forceinline__ uint32_t s2u(const void* p) {
    uint32_t a;
    asm("{ .reg .u64 t; cvta.to.shared.u64 t, %1; cvt.u32.u64 %0, t; }" : "=r"(a) : "l"(p));
    return a;
}
__device__ __forceinline__ void cp16(uint32_t dst, const void* src) {
    asm volatile("cp.async.cg.shared.global [%0], [%1], 16;" :: "r"(dst), "l"(src) : "memory");
}
__device__ __forceinline__ void ldsm_x4(uint32_t* r, uint32_t addr) {
    asm volatile("ldmatrix.sync.aligned.m8n8.x4.shared.b16 {%0,%1,%2,%3}, [%4];"
                 : "=r"(r[0]), "=r"(r[1]), "=r"(r[2]), "=r"(r[3]) : "r"(addr));
}
__device__ __forceinline__ void mma16816(float* d, const uint32_t* a, const uint32_t* b) {
    asm volatile(
        "mma.sync.aligned.m16n8k16.row.col.f32.bf16.bf16.f32 "
        "{%0,%1,%2,%3}, {%4,%5,%6,%7}, {%8,%9}, {%0,%1,%2,%3};"
        : "+f"(d[0]), "+f"(d[1]), "+f"(d[2]), "+f"(d[3])
        : "r"(a[0]), "r"(a[1]), "r"(a[2]), "r"(a[3]), "r"(b[0]), "r"(b[1]));
}

// ---------------- W1r precompute: W1r[o,h] = sum_p W_ctx[o, h*P+p] ----------
__global__ void k_w1r(const float* __restrict__ Wctx) {
    int o = blockIdx.x, h = threadIdx.x;
    const float* src = Wctx + (size_t)o * CTXW + h * Pn;
    float s = 0.f;
    #pragma unroll
    for (int p = 0; p < Pn; p++) s += src[p];
    g_W1r[o * Hn + h] = s;
}

// ---------------- prep B: g_Bw[p][o][h] = W_ctx[o,(H+h)*P+p] (+W1r at p=0) --
__global__ void k_prep_b(const float* __restrict__ Wctx) {
    __shared__ float w[8192];                 // w[h*64+p]
    int o = blockIdx.x, tid = threadIdx.x;
    const float* src = Wctx + (size_t)o * CTXW + Hn * Pn;
    for (int i = tid; i < 8192; i += 256) w[i] = src[i];
    __syncthreads();
    if (tid < Hn) w[tid * 64] += g_W1r[o * Hn + tid];
    __syncthreads();
    for (int i = tid; i < 8192; i += 256) {
        int p = i >> 7, h = i & 127;
        g_Bw[((size_t)p * 128 + o) * 128 + h] = __float2bfloat16(w[h * 64 + p]);
    }
}

// ---------------- Stage 1: gi = x @ W_ih^T  (4096 x 384 x 500) --------------
#define BM 64
#define BN 64
#define BK 16
__global__ void k_gemm_gi(const float* __restrict__ A, const float* __restrict__ W) {
    __shared__ float As[BK][BM + 1];
    __shared__ float Ws[BK][BN + 1];
    int m0 = blockIdx.y * BM, n0 = blockIdx.x * BN;
    int tid = threadIdx.x;
    int tx = tid & 15, ty = tid >> 4;
    float acc[4][4] = {};
    for (int k0 = 0; k0 < Fn; k0 += BK) {
        #pragma unroll
        for (int i = 0; i < 4; i++) {
            int e = tid + i * 256;
            int r = e >> 4, c = e & 15;
            int kk = k0 + c;
            As[c][r] = (kk < Fn) ? A[(size_t)(m0 + r) * Fn + kk] : 0.f;
        }
        #pragma unroll
        for (int i = 0; i < 4; i++) {
            int e = tid + i * 256;
            int r = e >> 4, c = e & 15;
            int kk = k0 + c;
            Ws[c][r] = (kk < Fn) ? W[(size_t)(n0 + r) * Fn + kk] : 0.f;
        }
        __syncthreads();
        #pragma unroll
        for (int k = 0; k < BK; k++) {
            float a[4], w[4];
            #pragma unroll
            for (int i = 0; i < 4; i++) a[i] = As[k][ty * 4 + i];
            #pragma unroll
            for (int j = 0; j < 4; j++) w[j] = Ws[k][tx * 4 + j];
            #pragma unroll
            for (int i = 0; i < 4; i++)
                #pragma unroll
                for (int j = 0; j < 4; j++)
                    acc[i][j] += a[i] * w[j];
        }
        __syncthreads();
    }
    #pragma unroll
    for (int i = 0; i < 4; i++)
        #pragma unroll
        for (int j = 0; j < 4; j++)
            g_gi[(size_t)(m0 + ty * 4 + i) * G3 + n0 + tx * 4 + j] = acc[i][j];
}

// ---------------- Stage 1b: gates -> states --------------------------------
__global__ void k_gates(const float* __restrict__ b_ih, const float* __restrict__ b_hh,
                        float* out_states) {
    int bt = blockIdx.x, h = threadIdx.x;
    int b = bt >> 10, t = bt & 1023;
    float* dst = out_states ? out_states : g_states_fallback;
    const float* gi = g_gi + (size_t)bt * G3;
    float r = 1.f / (1.f + expf(-(gi[h]        + b_ih[h]        + b_hh[h])));
    float z = 1.f / (1.f + expf(-(gi[Hn + h]   + b_ih[Hn + h]   + b_hh[Hn + h])));
    float n = tanhf(gi[2 * Hn + h] + b_ih[2 * Hn + h] + r * b_hh[2 * Hn + h]);
    float s = (1.f - z) * n;
    dst[((size_t)t * Bn + b) * Hn + h] = s;                  // all_states [T,B,H] exact
    g_states_bt[(size_t)bt * Hn + h] = s;
    __nv_bfloat16 sb = __float2bfloat16(s);
    g_Apad[((size_t)b * STP + PADOFF + t) * Hn + h] = sb;
    if (t == 0) {
        for (int j = 1; j < PADOFF; j++)
            g_Apad[((size_t)b * STP + j) * Hn + h] = sb;     // clip -> replicate s0
    }
}

// ---------------- Stage 2: context gate via mma.sync bf16 HMMA --------------
// CTA: 64 t x 64 o, K = 64 p-chunks x 128 h. grid (2 o, 16 t, 4 b) = 128 CTAs.
// A_p = shifted window of g_Apad (bf16); B_p = g_Bw[p] (bf16, [o][h]).
// Smem rows padded to 272B so ldmatrix is bank-conflict-free.
#define ROWB 272                         // bytes per smem row (136 bf16)
#define TILEB (64 * ROWB)                // 17408 per operand tile
__global__ void __launch_bounds__(256, 2)
k_ctx_mma(const float* __restrict__ b_ctx) {
    extern __shared__ char smem[];
    uint32_t sbase = s2u(smem);
    uint32_t Abuf[2] = { sbase,             sbase + 2 * TILEB };
    uint32_t Bbuf[2] = { sbase + TILEB,     sbase + 3 * TILEB };
    int tid = threadIdx.x;
    int o0 = blockIdx.x * 64, t0 = blockIdx.y * 64, b = blockIdx.z;
    int wid = tid >> 5, lane = tid & 31;
    int wr = wid >> 2, wc = wid & 3;     // warp tile: rows wr*32, cols wc*16

    const __nv_bfloat16* Asrc = g_Apad + (size_t)b * STP * Hn;

    // per-thread loader coords: 4 units of 16B each; tile = 64 rows x 16 units
    // (128 bf16 = 256B per row). FIXED from R6: u>>4 / u&15 (was u>>3 / u&7 -> OOB).
    int lr[4], lc[4];
    #pragma unroll
    for (int j = 0; j < 4; j++) { int u = tid + j * 256; lr[j] = u >> 4; lc[j] = u & 15; }

    float acc[2][2][4];
    #pragma unroll
    for (int i = 0; i < 2; i++)
        #pragma unroll
        for (int j = 0; j < 2; j++)
            #pragma unroll
            for (int k = 0; k < 4; k++) acc[i][j][k] = 0.f;

    // prologue: load chunk 0 into buffer 0
    #pragma unroll
    for (int j = 0; j < 4; j++) {
        cp16(Abuf[0] + lr[j] * ROWB + lc[j] * 16,
             Asrc + (size_t)(PADOFF + t0 + lr[j]) * Hn + lc[j] * 8);
        cp16(Bbuf[0] + lr[j] * ROWB + lc[j] * 16,
             g_Bw + ((size_t)0 * 128 + o0 + lr[j]) * 128 + lc[j] * 8);
    }
    asm volatile("cp.async.commit_group;" ::: "memory");

    // ldmatrix base addresses (per thread, within a buffer)
    // A: row = wr*32 + mt*16 + (lane&15), colb = (lane>>4)*16 + kk*32
    // B: row = wc*16 + ((lane>>4)&1)*8 + (lane&7), colb = ((lane>>3)&1)*16 + kk*32
    uint32_t aoff = (uint32_t)((wr * 32 + (lane & 15)) * ROWB + (lane >> 4) * 16);
    uint32_t boff = (uint32_t)((wc * 16 + ((lane >> 4) & 1) * 8 + (lane & 7)) * ROWB
                               + ((lane >> 3) & 1) * 16);

    for (int kc = 0; kc < 64; kc++) {
        int cur = kc & 1;
        if (kc + 1 < 64) {
            int nxt = cur ^ 1;
            int p = kc + 1;
            #pragma unroll
            for (int j = 0; j < 4; j++) {
                cp16(Abuf[nxt] + lr[j] * ROWB + lc[j] * 16,
                     Asrc + (size_t)(PADOFF + t0 + lr[j] - p) * Hn + lc[j] * 8);
                cp16(Bbuf[nxt] + lr[j] * ROWB + lc[j] * 16,
                     g_Bw + ((size_t)p * 128 + o0 + lr[j]) * 128 + lc[j] * 8);
            }
            asm volatile("cp.async.commit_group;" ::: "memory");
            asm volatile("cp.async.wait_group 1;" ::: "memory");
        } else {
            asm volatile("cp.async.wait_group 0;" ::: "memory");
        }
        __syncthreads();

        uint32_t Aa = Abuf[cur] + aoff;
        uint32_t Ba = Bbuf[cur] + boff;
        #pragma unroll
        for (int kk = 0; kk < 8; kk++) {
            uint32_t afr[2][4], bfr[4];
            ldsm_x4(afr[0], Aa + kk * 32);
            ldsm_x4(afr[1], Aa + 16 * ROWB + kk * 32);
            ldsm_x4(bfr,    Ba + kk * 32);
            #pragma unroll
            for (int mt = 0; mt < 2; mt++)
                #pragma unroll
                for (int nt = 0; nt < 2; nt++)
                    mma16816(acc[mt][nt], afr[mt], bfr + 2 * nt);
        }
        __syncthreads();
    }

    // epilogue: gate = sigmoid(acc + b_ctx); gated = state * gate
    int rbase = t0 + wr * 32 + (lane >> 2);
    int cbase = o0 + wc * 16 + (lane & 3) * 2;
    #pragma unroll
    for (int mt = 0; mt < 2; mt++) {
        #pragma unroll
        for (int nt = 0; nt < 2; nt++) {
            #pragma unroll
            for (int e = 0; e < 4; e++) {
                int R = rbase + mt * 16 + (e >> 1) * 8;
                int C = cbase + nt * 8 + (e & 1);
                float y = acc[mt][nt][e] + b_ctx[C];
                float gate = 1.f / (1.f + expf(-y));
                float s = g_states_bt[((size_t)b * Tn + R) * Hn + C];
                g_gated[((size_t)b * Tn + R) * Hn + C] = s * gate;
            }
        }
    }
}

// ---------------- Stage 3: probs = clip(sigmoid(gated @ W_fc^T + b_fc)) -----
__global__ void k_probs(const float* __restrict__ Wfc, const float* __restrict__ b_fc,
                        float* __restrict__ probs) {
    __shared__ float gs[64][33];
    __shared__ float wf[64][33];
    int r0 = blockIdx.x * 64;
    int tid = threadIdx.x, tx = tid & 15, ty = tid >> 4;
    float acc[4][4] = {};
    for (int k0 = 0; k0 < Hn; k0 += 32) {
        #pragma unroll
        for (int i = 0; i < 8; i++) {
            int e = tid + i * 256;
            int r = e >> 5, c = e & 31;
            gs[r][c] = g_gated[(size_t)(r0 + r) * Hn + k0 + c];
            wf[r][c] = Wfc[(size_t)r * Hn + k0 + c];
        }
        __syncthreads();
        #pragma unroll
        for (int k = 0; k < 32; k++) {
            float a[4], w[4];
            #pragma unroll
            for (int i = 0; i < 4; i++) a[i] = gs[ty * 4 + i][k];
            #pragma unroll
            for (int j = 0; j < 4; j++) w[j] = wf[tx * 4 + j][k];
            #pragma unroll
            for (int i = 0; i < 4; i++)
                #pragma unroll
                for (int j = 0; j < 4; j++) acc[i][j] += a[i] * w[j];
        }
        __syncthreads();
    }
    #pragma unroll
    for (int i = 0; i < 4; i++) {
        int row = r0 + ty * 4 + i;
        #pragma unroll
        for (int j = 0; j < 4; j++) {
            int p = tx * 4 + j;
            float y = acc[i][j] + b_fc[p];
            float pr = 1.f / (1.f + expf(-y));
            pr = fminf(fmaxf(pr, 0.001f), 0.999f);
            probs[(size_t)row * Pn + p] = pr;
        }
    }
}

// ---------------- launch -----------------------------------------------------
extern "C" void kernel_launch(void* const* d_in, const int* in_sizes, int n_in,
                              void* d_out, int out_size) {
    const float* x     = (const float*)d_in[0];
    const float* W_ih  = (const float*)d_in[1];
    // d_in[2] = W_hh (unused: hidden state is always zero in the reference)
    const float* b_ih  = (const float*)d_in[3];
    const float* b_hh  = (const float*)d_in[4];
    const float* W_ctx = (const float*)d_in[5];
    const float* b_ctx = (const float*)d_in[6];
    const float* W_fc  = (const float*)d_in[7];
    const float* b_fc  = (const float*)d_in[8];

    float* out = (float*)d_out;
    const int PROBS_N = Bn * Tn * Pn;            // 262144
    const int TOTAL_N = PROBS_N + Tn * Bn * Hn;  // 786432
    float* out_probs  = out;
    float* out_states = (out_size >= TOTAL_N) ? (out + PROBS_N) : nullptr;

    // idempotent, unconditionally each call (no static guards per harness rules)
    cudaFuncSetAttribute(k_ctx_mma, cudaFuncAttributeMaxDynamicSharedMemorySize, 4 * TILEB);

    k_w1r<<<Hn, Hn>>>(W_ctx);
    k_prep_b<<<Hn, 256>>>(W_ctx);
    k_gemm_gi<<<dim3(G3 / BN, (Bn * Tn) / BM), 256>>>(x, W_ih);
    k_gates<<<Bn * Tn, Hn>>>(b_ih, b_hh, out_states);
    k_ctx_mma<<<dim3(2, Tn / 64, Bn), 256, 4 * TILEB>>>(b_ctx);
    k_probs<<<(Bn * Tn) / 64, 256>>>(W_fc, b_fc, out_probs);
}

// round 8
// speedup vs baseline: 3.3743x; 1.5687x over previous
#include <cuda_runtime.h>
#include <cuda_bf16.h>
#include <math.h>
#include <stdint.h>

// Problem dims
#define Bn   4
#define Tn   1024
#define Fn   500
#define Hn   128
#define Pn   64
#define G3   384          // 3*H
#define CTXW 16384        // 2*H*P
#define STP  1088         // padded time rows (64 left pad + 1024)
#define PADOFF 64
#define KP   512          // padded K for gi GEMM (500 -> 512)

// Scratch (__device__ globals: no allocation allowed)
__device__ float g_gi[Bn*Tn*G3];                 // 6.3 MB
__device__ float g_states_bt[Bn*Tn*Hn];          // 2 MB   [b*T+t, h] fp32 exact
__device__ __nv_bfloat16 g_Apad[Bn*STP*Hn];      // 1.1 MB [b][64+t][h] bf16 (rows 1..63 = s0)
__device__ float g_gated[Bn*Tn*Hn];              // 2 MB
__device__ __nv_bfloat16 g_Bw[64*128*128];       // 2 MB: [p][o][h] bf16, W1r folded at p=0
__device__ float g_states_fallback[Tn*Bn*Hn];
// bf16 split operands for gi GEMM
__device__ __nv_bfloat16 g_xhi[Bn*Tn*KP];        // 4 MB
__device__ __nv_bfloat16 g_xlo[Bn*Tn*KP];        // 4 MB
__device__ __nv_bfloat16 g_Whi[G3*KP];           // 384 KB
__device__ __nv_bfloat16 g_Wlo[G3*KP];           // 384 KB

// ---------------- helpers ----------------------------------------------------
__device__ __forceinline__ uint32_t s2u(const void* p) {
    uint32_t a;
    asm("{ .reg .u64 t; cvta.to.shared.u64 t, %1; cvt.u32.u64 %0, t; }" : "=r"(a) : "l"(p));
    return a;
}
__device__ __forceinline__ void cp16(uint32_t dst, const void* src) {
    asm volatile("cp.async.cg.shared.global [%0], [%1], 16;" :: "r"(dst), "l"(src) : "memory");
}
__device__ __forceinline__ void ldsm_x4(uint32_t* r, uint32_t addr) {
    asm volatile("ldmatrix.sync.aligned.m8n8.x4.shared.b16 {%0,%1,%2,%3}, [%4];"
                 : "=r"(r[0]), "=r"(r[1]), "=r"(r[2]), "=r"(r[3]) : "r"(addr));
}
__device__ __forceinline__ void mma16816(float* d, const uint32_t* a, const uint32_t* b) {
    asm volatile(
        "mma.sync.aligned.m16n8k16.row.col.f32.bf16.bf16.f32 "
        "{%0,%1,%2,%3}, {%4,%5,%6,%7}, {%8,%9}, {%0,%1,%2,%3};"
        : "+f"(d[0]), "+f"(d[1]), "+f"(d[2]), "+f"(d[3])
        : "r"(a[0]), "r"(a[1]), "r"(a[2]), "r"(a[3]), "r"(b[0]), "r"(b[1]));
}

// ---------------- k_prep: all weight/input preprocessing in one launch -------
// blocks [0,128):      B-prep for o = blockIdx.x (W1r fold + [p][o][h] layout)
// blocks [128,4224):   x row split -> g_xhi/g_xlo (row = blockIdx.x-128)
// blocks [4224,4608):  W_ih row split -> g_Whi/g_Wlo
__global__ void k_prep(const float* __restrict__ Wctx,
                       const float* __restrict__ x,
                       const float* __restrict__ Wih) {
    int blk = blockIdx.x, tid = threadIdx.x;
    if (blk < 128) {
        __shared__ float w[8192];
        __shared__ float w1r[128];
        int o = blk;
        // part1 weights: W1r[h] = sum_p Wctx[o, h*64+p]
        const float* src1 = Wctx + (size_t)o * CTXW;
        for (int i = tid; i < 8192; i += 256) w[i] = src1[i];
        __syncthreads();
        if (tid < 128) {
            float s = 0.f;
            #pragma unroll
            for (int p = 0; p < 64; p++) s += w[tid * 64 + p];
            w1r[tid] = s;
        }
        __syncthreads();
        // part2 weights
        const float* src2 = Wctx + (size_t)o * CTXW + Hn * Pn;
        for (int i = tid; i < 8192; i += 256) w[i] = src2[i];
        __syncthreads();
        if (tid < 128) w[tid * 64] += w1r[tid];
        __syncthreads();
        for (int i = tid; i < 8192; i += 256) {
            int p = i >> 7, h = i & 127;
            g_Bw[((size_t)p * 128 + o) * 128 + h] = __float2bfloat16(w[h * 64 + p]);
        }
    } else if (blk < 128 + Bn * Tn) {
        int r = blk - 128;
        const float* src = x + (size_t)r * Fn;
        for (int c = tid; c < KP; c += 256) {
            float v = (c < Fn) ? src[c] : 0.f;
            __nv_bfloat16 hi = __float2bfloat16(v);
            __nv_bfloat16 lo = __float2bfloat16(v - __bfloat162float(hi));
            g_xhi[(size_t)r * KP + c] = hi;
            g_xlo[(size_t)r * KP + c] = lo;
        }
    } else {
        int r = blk - 128 - Bn * Tn;
        const float* src = Wih + (size_t)r * Fn;
        for (int c = tid; c < KP; c += 256) {
            float v = (c < Fn) ? src[c] : 0.f;
            __nv_bfloat16 hi = __float2bfloat16(v);
            __nv_bfloat16 lo = __float2bfloat16(v - __bfloat162float(hi));
            g_Whi[(size_t)r * KP + c] = hi;
            g_Wlo[(size_t)r * KP + c] = lo;
        }
    }
}

// ---------------- Stage 1: gi = x @ W_ih^T via split-bf16 HMMA --------------
// M=4096, N=384, K=512. CTA 64m x 64n, grid (6, 64). K-chunks of 64.
// acc += xhi*Whi + xhi*Wlo + xlo*Whi  (xlo*Wlo negligible ~1e-5)
#define GROWB 144                        // 64 bf16 = 128B + 16 pad
#define GTILE (64 * GROWB)               // 9216 B
__global__ void __launch_bounds__(256, 2)
k_gemm_gi(const float* __restrict__ dummy) {
    extern __shared__ char smem[];
    uint32_t sbase = s2u(smem);
    // per stage: [Axhi][Axlo][Bwhi][Bwlo]
    uint32_t st[2];
    st[0] = sbase; st[1] = sbase + 4 * GTILE;
    int tid = threadIdx.x;
    int n0 = blockIdx.x * 64, m0 = blockIdx.y * 64;
    int wid = tid >> 5, lane = tid & 31;
    int wr = wid >> 2, wc = wid & 3;     // warp tile rows wr*32, cols wc*16

    // loader coords: per tile 64 rows x 8 units(16B); 512 units/tile, 2/thread
    int lr[2], lc[2];
    #pragma unroll
    for (int j = 0; j < 2; j++) { int u = tid + j * 256; lr[j] = u >> 3; lc[j] = u & 7; }

    float acc[2][2][4];
    #pragma unroll
    for (int i = 0; i < 2; i++)
        #pragma unroll
        for (int j = 0; j < 2; j++)
            #pragma unroll
            for (int k = 0; k < 4; k++) acc[i][j][k] = 0.f;

    // prologue chunk 0
    #pragma unroll
    for (int j = 0; j < 2; j++) {
        uint32_t d = lr[j] * GROWB + lc[j] * 16;
        size_t so = (size_t)lc[j] * 8;
        cp16(st[0] + 0 * GTILE + d, g_xhi + (size_t)(m0 + lr[j]) * KP + so);
        cp16(st[0] + 1 * GTILE + d, g_xlo + (size_t)(m0 + lr[j]) * KP + so);
        cp16(st[0] + 2 * GTILE + d, g_Whi + (size_t)(n0 + lr[j]) * KP + so);
        cp16(st[0] + 3 * GTILE + d, g_Wlo + (size_t)(n0 + lr[j]) * KP + so);
    }
    asm volatile("cp.async.commit_group;" ::: "memory");

    uint32_t aoff = (uint32_t)((wr * 32 + (lane & 15)) * GROWB + (lane >> 4) * 16);
    uint32_t boff = (uint32_t)((wc * 16 + ((lane >> 4) & 1) * 8 + (lane & 7)) * GROWB
                               + ((lane >> 3) & 1) * 16);

    for (int kc = 0; kc < 8; kc++) {
        int cur = kc & 1;
        if (kc + 1 < 8) {
            int nxt = cur ^ 1;
            int k0 = (kc + 1) * 64;
            #pragma unroll
            for (int j = 0; j < 2; j++) {
                uint32_t d = lr[j] * GROWB + lc[j] * 16;
                size_t so = (size_t)k0 + lc[j] * 8;
                cp16(st[nxt] + 0 * GTILE + d, g_xhi + (size_t)(m0 + lr[j]) * KP + so);
                cp16(st[nxt] + 1 * GTILE + d, g_xlo + (size_t)(m0 + lr[j]) * KP + so);
                cp16(st[nxt] + 2 * GTILE + d, g_Whi + (size_t)(n0 + lr[j]) * KP + so);
                cp16(st[nxt] + 3 * GTILE + d, g_Wlo + (size_t)(n0 + lr[j]) * KP + so);
            }
            asm volatile("cp.async.commit_group;" ::: "memory");
            asm volatile("cp.async.wait_group 1;" ::: "memory");
        } else {
            asm volatile("cp.async.wait_group 0;" ::: "memory");
        }
        __syncthreads();

        uint32_t Ah = st[cur] + 0 * GTILE + aoff;
        uint32_t Al = st[cur] + 1 * GTILE + aoff;
        uint32_t Bh = st[cur] + 2 * GTILE + boff;
        uint32_t Bl = st[cur] + 3 * GTILE + boff;
        #pragma unroll
        for (int kk = 0; kk < 4; kk++) {
            uint32_t ah[2][4], al[2][4], bh[4], bl[4];
            ldsm_x4(ah[0], Ah + kk * 32);
            ldsm_x4(ah[1], Ah + 16 * GROWB + kk * 32);
            ldsm_x4(al[0], Al + kk * 32);
            ldsm_x4(al[1], Al + 16 * GROWB + kk * 32);
            ldsm_x4(bh,    Bh + kk * 32);
            ldsm_x4(bl,    Bl + kk * 32);
            #pragma unroll
            for (int mt = 0; mt < 2; mt++)
                #pragma unroll
                for (int nt = 0; nt < 2; nt++) {
                    mma16816(acc[mt][nt], ah[mt], bh + 2 * nt);
                    mma16816(acc[mt][nt], ah[mt], bl + 2 * nt);
                    mma16816(acc[mt][nt], al[mt], bh + 2 * nt);
                }
        }
        __syncthreads();
    }

    // epilogue: write gi fp32
    int rbase = m0 + wr * 32 + (lane >> 2);
    int cbase = n0 + wc * 16 + (lane & 3) * 2;
    #pragma unroll
    for (int mt = 0; mt < 2; mt++)
        #pragma unroll
        for (int nt = 0; nt < 2; nt++)
            #pragma unroll
            for (int e = 0; e < 4; e++) {
                int R = rbase + mt * 16 + (e >> 1) * 8;
                int C = cbase + nt * 8 + (e & 1);
                g_gi[(size_t)R * G3 + C] = acc[mt][nt][e];
            }
}

// ---------------- Stage 1b: gates -> states --------------------------------
__global__ void k_gates(const float* __restrict__ b_ih, const float* __restrict__ b_hh,
                        float* out_states) {
    int bt = blockIdx.x, h = threadIdx.x;
    int b = bt >> 10, t = bt & 1023;
    float* dst = out_states ? out_states : g_states_fallback;
    const float* gi = g_gi + (size_t)bt * G3;
    float r = 1.f / (1.f + expf(-(gi[h]        + b_ih[h]        + b_hh[h])));
    float z = 1.f / (1.f + expf(-(gi[Hn + h]   + b_ih[Hn + h]   + b_hh[Hn + h])));
    float n = tanhf(gi[2 * Hn + h] + b_ih[2 * Hn + h] + r * b_hh[2 * Hn + h]);
    float s = (1.f - z) * n;
    dst[((size_t)t * Bn + b) * Hn + h] = s;                  // all_states [T,B,H] exact
    g_states_bt[(size_t)bt * Hn + h] = s;
    __nv_bfloat16 sb = __float2bfloat16(s);
    g_Apad[((size_t)b * STP + PADOFF + t) * Hn + h] = sb;
    if (t == 0) {
        for (int j = 1; j < PADOFF; j++)
            g_Apad[((size_t)b * STP + j) * Hn + h] = sb;     // clip -> replicate s0
    }
}

// ---------------- Stage 2: context gate via mma.sync bf16 HMMA --------------
// (unchanged from R7 — proven correct)
#define ROWB 272
#define TILEB (64 * ROWB)
__global__ void __launch_bounds__(256, 2)
k_ctx_mma(const float* __restrict__ b_ctx) {
    extern __shared__ char smem[];
    uint32_t sbase = s2u(smem);
    uint32_t Abuf[2] = { sbase,             sbase + 2 * TILEB };
    uint32_t Bbuf[2] = { sbase + TILEB,     sbase + 3 * TILEB };
    int tid = threadIdx.x;
    int o0 = blockIdx.x * 64, t0 = blockIdx.y * 64, b = blockIdx.z;
    int wid = tid >> 5, lane = tid & 31;
    int wr = wid >> 2, wc = wid & 3;

    const __nv_bfloat16* Asrc = g_Apad + (size_t)b * STP * Hn;

    int lr[4], lc[4];
    #pragma unroll
    for (int j = 0; j < 4; j++) { int u = tid + j * 256; lr[j] = u >> 4; lc[j] = u & 15; }

    float acc[2][2][4];
    #pragma unroll
    for (int i = 0; i < 2; i++)
        #pragma unroll
        for (int j = 0; j < 2; j++)
            #pragma unroll
            for (int k = 0; k < 4; k++) acc[i][j][k] = 0.f;

    #pragma unroll
    for (int j = 0; j < 4; j++) {
        cp16(Abuf[0] + lr[j] * ROWB + lc[j] * 16,
             Asrc + (size_t)(PADOFF + t0 + lr[j]) * Hn + lc[j] * 8);
        cp16(Bbuf[0] + lr[j] * ROWB + lc[j] * 16,
             g_Bw + ((size_t)0 * 128 + o0 + lr[j]) * 128 + lc[j] * 8);
    }
    asm volatile("cp.async.commit_group;" ::: "memory");

    uint32_t aoff = (uint32_t)((wr * 32 + (lane & 15)) * ROWB + (lane >> 4) * 16);
    uint32_t boff = (uint32_t)((wc * 16 + ((lane >> 4) & 1) * 8 + (lane & 7)) * ROWB
                               + ((lane >> 3) & 1) * 16);

    for (int kc = 0; kc < 64; kc++) {
        int cur = kc & 1;
        if (kc + 1 < 64) {
            int nxt = cur ^ 1;
            int p = kc + 1;
            #pragma unroll
            for (int j = 0; j < 4; j++) {
                cp16(Abuf[nxt] + lr[j] * ROWB + lc[j] * 16,
                     Asrc + (size_t)(PADOFF + t0 + lr[j] - p) * Hn + lc[j] * 8);
                cp16(Bbuf[nxt] + lr[j] * ROWB + lc[j] * 16,
                     g_Bw + ((size_t)p * 128 + o0 + lr[j]) * 128 + lc[j] * 8);
            }
            asm volatile("cp.async.commit_group;" ::: "memory");
            asm volatile("cp.async.wait_group 1;" ::: "memory");
        } else {
            asm volatile("cp.async.wait_group 0;" ::: "memory");
        }
        __syncthreads();

        uint32_t Aa = Abuf[cur] + aoff;
        uint32_t Ba = Bbuf[cur] + boff;
        #pragma unroll
        for (int kk = 0; kk < 8; kk++) {
            uint32_t afr[2][4], bfr[4];
            ldsm_x4(afr[0], Aa + kk * 32);
            ldsm_x4(afr[1], Aa + 16 * ROWB + kk * 32);
            ldsm_x4(bfr,    Ba + kk * 32);
            #pragma unroll
            for (int mt = 0; mt < 2; mt++)
                #pragma unroll
                for (int nt = 0; nt < 2; nt++)
                    mma16816(acc[mt][nt], afr[mt], bfr + 2 * nt);
        }
        __syncthreads();
    }

    int rbase = t0 + wr * 32 + (lane >> 2);
    int cbase = o0 + wc * 16 + (lane & 3) * 2;
    #pragma unroll
    for (int mt = 0; mt < 2; mt++) {
        #pragma unroll
        for (int nt = 0; nt < 2; nt++) {
            #pragma unroll
            for (int e = 0; e < 4; e++) {
                int R = rbase + mt * 16 + (e >> 1) * 8;
                int C = cbase + nt * 8 + (e & 1);
                float y = acc[mt][nt][e] + b_ctx[C];
                float gate = 1.f / (1.f + expf(-y));
                float s = g_states_bt[((size_t)b * Tn + R) * Hn + C];
                g_gated[((size_t)b * Tn + R) * Hn + C] = s * gate;
            }
        }
    }
}

// ---------------- Stage 3: probs = clip(sigmoid(gated @ W_fc^T + b_fc)) -----
__global__ void k_probs(const float* __restrict__ Wfc, const float* __restrict__ b_fc,
                        float* __restrict__ probs) {
    __shared__ float gs[64][33];
    __shared__ float wf[64][33];
    int r0 = blockIdx.x * 64;
    int tid = threadIdx.x, tx = tid & 15, ty = tid >> 4;
    float acc[4][4] = {};
    for (int k0 = 0; k0 < Hn; k0 += 32) {
        #pragma unroll
        for (int i = 0; i < 8; i++) {
            int e = tid + i * 256;
            int r = e >> 5, c = e & 31;
            gs[r][c] = g_gated[(size_t)(r0 + r) * Hn + k0 + c];
            wf[r][c] = Wfc[(size_t)r * Hn + k0 + c];
        }
        __syncthreads();
        #pragma unroll
        for (int k = 0; k < 32; k++) {
            float a[4], w[4];
            #pragma unroll
            for (int i = 0; i < 4; i++) a[i] = gs[ty * 4 + i][k];
            #pragma unroll
            for (int j = 0; j < 4; j++) w[j] = wf[tx * 4 + j][k];
            #pragma unroll
            for (int i = 0; i < 4; i++)
                #pragma unroll
                for (int j = 0; j < 4; j++) acc[i][j] += a[i] * w[j];
        }
        __syncthreads();
    }
    #pragma unroll
    for (int i = 0; i < 4; i++) {
        int row = r0 + ty * 4 + i;
        #pragma unroll
        for (int j = 0; j < 4; j++) {
            int p = tx * 4 + j;
            float y = acc[i][j] + b_fc[p];
            float pr = 1.f / (1.f + expf(-y));
            pr = fminf(fmaxf(pr, 0.001f), 0.999f);
            probs[(size_t)row * Pn + p] = pr;
        }
    }
}

// ---------------- launch -----------------------------------------------------
extern "C" void kernel_launch(void* const* d_in, const int* in_sizes, int n_in,
                              void* d_out, int out_size) {
    const float* x     = (const float*)d_in[0];
    const float* W_ih  = (const float*)d_in[1];
    // d_in[2] = W_hh (unused: hidden state is always zero in the reference)
    const float* b_ih  = (const float*)d_in[3];
    const float* b_hh  = (const float*)d_in[4];
    const float* W_ctx = (const float*)d_in[5];
    const float* b_ctx = (const float*)d_in[6];
    const float* W_fc  = (const float*)d_in[7];
    const float* b_fc  = (const float*)d_in[8];

    float* out = (float*)d_out;
    const int PROBS_N = Bn * Tn * Pn;            // 262144
    const int TOTAL_N = PROBS_N + Tn * Bn * Hn;  // 786432
    float* out_probs  = out;
    float* out_states = (out_size >= TOTAL_N) ? (out + PROBS_N) : nullptr;

    // idempotent, unconditionally each call (no static guards per harness rules)
    cudaFuncSetAttribute(k_ctx_mma, cudaFuncAttributeMaxDynamicSharedMemorySize, 4 * TILEB);
    cudaFuncSetAttribute(k_gemm_gi, cudaFuncAttributeMaxDynamicSharedMemorySize, 8 * GTILE);

    k_prep<<<128 + Bn * Tn + G3, 256>>>(W_ctx, x, W_ih);
    k_gemm_gi<<<dim3(G3 / 64, (Bn * Tn) / 64), 256, 8 * GTILE>>>(nullptr);
    k_gates<<<Bn * Tn, Hn>>>(b_ih, b_hh, out_states);
    k_ctx_mma<<<dim3(2, Tn / 64, Bn), 256, 4 * TILEB>>>(b_ctx);
    k_probs<<<(Bn * Tn) / 64, 256>>>(W_fc, b_fc, out_probs);
}

// round 9
// speedup vs baseline: 3.8682x; 1.1464x over previous
#include <cuda_runtime.h>
#include <cuda_bf16.h>
#include <math.h>
#include <stdint.h>

// Problem dims
#define Bn   4
#define Tn   1024
#define Fn   500
#define Hn   128
#define Pn   64
#define G3   384          // 3*H
#define CTXW 16384        // 2*H*P
#define STP  1088         // padded time rows (64 left pad + 1024)
#define PADOFF 64
#define KP   512          // padded K for gi GEMM (500 -> 512)

// Scratch (__device__ globals: no allocation allowed)
__device__ float g_gi[Bn*Tn*G3];                 // 6.3 MB
__device__ float g_states_bt[Bn*Tn*Hn];          // 2 MB   [b*T+t, h] fp32 exact
__device__ __nv_bfloat16 g_Apad[Bn*STP*Hn];      // 1.1 MB [b][64+t][h] bf16 (rows 1..63 = s0)
__device__ float g_gated[Bn*Tn*Hn];              // 2 MB
__device__ __nv_bfloat16 g_Bw[64*128*128];       // 2 MB: [p][o][h] bf16, W1r folded at p=0
__device__ float g_states_fallback[Tn*Bn*Hn];
// bf16 split operands for gi GEMM
__device__ __nv_bfloat16 g_xhi[Bn*Tn*KP];        // 4 MB
__device__ __nv_bfloat16 g_xlo[Bn*Tn*KP];        // 4 MB
__device__ __nv_bfloat16 g_Whi[G3*KP];           // 384 KB
__device__ __nv_bfloat16 g_Wlo[G3*KP];           // 384 KB

// ---------------- helpers ----------------------------------------------------
__device__ __forceinline__ uint32_t s2u(const void* p) {
    uint32_t a;
    asm("{ .reg .u64 t; cvta.to.shared.u64 t, %1; cvt.u32.u64 %0, t; }" : "=r"(a) : "l"(p));
    return a;
}
__device__ __forceinline__ void cp16(uint32_t dst, const void* src) {
    asm volatile("cp.async.cg.shared.global [%0], [%1], 16;" :: "r"(dst), "l"(src) : "memory");
}
__device__ __forceinline__ void ldsm_x4(uint32_t* r, uint32_t addr) {
    asm volatile("ldmatrix.sync.aligned.m8n8.x4.shared.b16 {%0,%1,%2,%3}, [%4];"
                 : "=r"(r[0]), "=r"(r[1]), "=r"(r[2]), "=r"(r[3]) : "r"(addr));
}
__device__ __forceinline__ void mma16816(float* d, const uint32_t* a, const uint32_t* b) {
    asm volatile(
        "mma.sync.aligned.m16n8k16.row.col.f32.bf16.bf16.f32 "
        "{%0,%1,%2,%3}, {%4,%5,%6,%7}, {%8,%9}, {%0,%1,%2,%3};"
        : "+f"(d[0]), "+f"(d[1]), "+f"(d[2]), "+f"(d[3])
        : "r"(a[0]), "r"(a[1]), "r"(a[2]), "r"(a[3]), "r"(b[0]), "r"(b[1]));
}

// ---------------- k_prep: all weight/input preprocessing in one launch -------
__global__ void k_prep(const float* __restrict__ Wctx,
                       const float* __restrict__ x,
                       const float* __restrict__ Wih) {
    int blk = blockIdx.x, tid = threadIdx.x;
    if (blk < 128) {
        __shared__ float w[8192];
        __shared__ float w1r[128];
        int o = blk;
        const float* src1 = Wctx + (size_t)o * CTXW;
        for (int i = tid; i < 8192; i += 256) w[i] = src1[i];
        __syncthreads();
        if (tid < 128) {
            float s = 0.f;
            #pragma unroll
            for (int p = 0; p < 64; p++) s += w[tid * 64 + p];
            w1r[tid] = s;
        }
        __syncthreads();
        const float* src2 = Wctx + (size_t)o * CTXW + Hn * Pn;
        for (int i = tid; i < 8192; i += 256) w[i] = src2[i];
        __syncthreads();
        if (tid < 128) w[tid * 64] += w1r[tid];
        __syncthreads();
        for (int i = tid; i < 8192; i += 256) {
            int p = i >> 7, h = i & 127;
            g_Bw[((size_t)p * 128 + o) * 128 + h] = __float2bfloat16(w[h * 64 + p]);
        }
    } else if (blk < 128 + Bn * Tn) {
        int r = blk - 128;
        const float* src = x + (size_t)r * Fn;
        for (int c = tid; c < KP; c += 256) {
            float v = (c < Fn) ? src[c] : 0.f;
            __nv_bfloat16 hi = __float2bfloat16(v);
            __nv_bfloat16 lo = __float2bfloat16(v - __bfloat162float(hi));
            g_xhi[(size_t)r * KP + c] = hi;
            g_xlo[(size_t)r * KP + c] = lo;
        }
    } else {
        int r = blk - 128 - Bn * Tn;
        const float* src = Wih + (size_t)r * Fn;
        for (int c = tid; c < KP; c += 256) {
            float v = (c < Fn) ? src[c] : 0.f;
            __nv_bfloat16 hi = __float2bfloat16(v);
            __nv_bfloat16 lo = __float2bfloat16(v - __bfloat162float(hi));
            g_Whi[(size_t)r * KP + c] = hi;
            g_Wlo[(size_t)r * KP + c] = lo;
        }
    }
}

// ---------------- Stage 1: gi = x @ W_ih^T via split-bf16 HMMA --------------
#define GROWB 144
#define GTILE (64 * GROWB)
__global__ void __launch_bounds__(256, 2)
k_gemm_gi(const float* __restrict__ dummy) {
    extern __shared__ char smem[];
    uint32_t sbase = s2u(smem);
    uint32_t st[2];
    st[0] = sbase; st[1] = sbase + 4 * GTILE;
    int tid = threadIdx.x;
    int n0 = blockIdx.x * 64, m0 = blockIdx.y * 64;
    int wid = tid >> 5, lane = tid & 31;
    int wr = wid >> 2, wc = wid & 3;

    int lr[2], lc[2];
    #pragma unroll
    for (int j = 0; j < 2; j++) { int u = tid + j * 256; lr[j] = u >> 3; lc[j] = u & 7; }

    float acc[2][2][4];
    #pragma unroll
    for (int i = 0; i < 2; i++)
        #pragma unroll
        for (int j = 0; j < 2; j++)
            #pragma unroll
            for (int k = 0; k < 4; k++) acc[i][j][k] = 0.f;

    #pragma unroll
    for (int j = 0; j < 2; j++) {
        uint32_t d = lr[j] * GROWB + lc[j] * 16;
        size_t so = (size_t)lc[j] * 8;
        cp16(st[0] + 0 * GTILE + d, g_xhi + (size_t)(m0 + lr[j]) * KP + so);
        cp16(st[0] + 1 * GTILE + d, g_xlo + (size_t)(m0 + lr[j]) * KP + so);
        cp16(st[0] + 2 * GTILE + d, g_Whi + (size_t)(n0 + lr[j]) * KP + so);
        cp16(st[0] + 3 * GTILE + d, g_Wlo + (size_t)(n0 + lr[j]) * KP + so);
    }
    asm volatile("cp.async.commit_group;" ::: "memory");

    uint32_t aoff = (uint32_t)((wr * 32 + (lane & 15)) * GROWB + (lane >> 4) * 16);
    uint32_t boff = (uint32_t)((wc * 16 + ((lane >> 4) & 1) * 8 + (lane & 7)) * GROWB
                               + ((lane >> 3) & 1) * 16);

    for (int kc = 0; kc < 8; kc++) {
        int cur = kc & 1;
        if (kc + 1 < 8) {
            int nxt = cur ^ 1;
            int k0 = (kc + 1) * 64;
            #pragma unroll
            for (int j = 0; j < 2; j++) {
                uint32_t d = lr[j] * GROWB + lc[j] * 16;
                size_t so = (size_t)k0 + lc[j] * 8;
                cp16(st[nxt] + 0 * GTILE + d, g_xhi + (size_t)(m0 + lr[j]) * KP + so);
                cp16(st[nxt] + 1 * GTILE + d, g_xlo + (size_t)(m0 + lr[j]) * KP + so);
                cp16(st[nxt] + 2 * GTILE + d, g_Whi + (size_t)(n0 + lr[j]) * KP + so);
                cp16(st[nxt] + 3 * GTILE + d, g_Wlo + (size_t)(n0 + lr[j]) * KP + so);
            }
            asm volatile("cp.async.commit_group;" ::: "memory");
            asm volatile("cp.async.wait_group 1;" ::: "memory");
        } else {
            asm volatile("cp.async.wait_group 0;" ::: "memory");
        }
        __syncthreads();

        uint32_t Ah = st[cur] + 0 * GTILE + aoff;
        uint32_t Al = st[cur] + 1 * GTILE + aoff;
        uint32_t Bh = st[cur] + 2 * GTILE + boff;
        uint32_t Bl = st[cur] + 3 * GTILE + boff;
        #pragma unroll
        for (int kk = 0; kk < 4; kk++) {
            uint32_t ah[2][4], al[2][4], bh[4], bl[4];
            ldsm_x4(ah[0], Ah + kk * 32);
            ldsm_x4(ah[1], Ah + 16 * GROWB + kk * 32);
            ldsm_x4(al[0], Al + kk * 32);
            ldsm_x4(al[1], Al + 16 * GROWB + kk * 32);
            ldsm_x4(bh,    Bh + kk * 32);
            ldsm_x4(bl,    Bl + kk * 32);
            #pragma unroll
            for (int mt = 0; mt < 2; mt++)
                #pragma unroll
                for (int nt = 0; nt < 2; nt++) {
                    mma16816(acc[mt][nt], ah[mt], bh + 2 * nt);
                    mma16816(acc[mt][nt], ah[mt], bl + 2 * nt);
                    mma16816(acc[mt][nt], al[mt], bh + 2 * nt);
                }
        }
        __syncthreads();
    }

    int rbase = m0 + wr * 32 + (lane >> 2);
    int cbase = n0 + wc * 16 + (lane & 3) * 2;
    #pragma unroll
    for (int mt = 0; mt < 2; mt++)
        #pragma unroll
        for (int nt = 0; nt < 2; nt++)
            #pragma unroll
            for (int e = 0; e < 4; e++) {
                int R = rbase + mt * 16 + (e >> 1) * 8;
                int C = cbase + nt * 8 + (e & 1);
                g_gi[(size_t)R * G3 + C] = acc[mt][nt][e];
            }
}

// ---------------- Stage 1b: gates -> states --------------------------------
__global__ void k_gates(const float* __restrict__ b_ih, const float* __restrict__ b_hh,
                        float* out_states) {
    int bt = blockIdx.x, h = threadIdx.x;
    int b = bt >> 10, t = bt & 1023;
    float* dst = out_states ? out_states : g_states_fallback;
    const float* gi = g_gi + (size_t)bt * G3;
    float r = 1.f / (1.f + expf(-(gi[h]        + b_ih[h]        + b_hh[h])));
    float z = 1.f / (1.f + expf(-(gi[Hn + h]   + b_ih[Hn + h]   + b_hh[Hn + h])));
    float n = tanhf(gi[2 * Hn + h] + b_ih[2 * Hn + h] + r * b_hh[2 * Hn + h]);
    float s = (1.f - z) * n;
    dst[((size_t)t * Bn + b) * Hn + h] = s;                  // all_states [T,B,H] exact
    g_states_bt[(size_t)bt * Hn + h] = s;
    __nv_bfloat16 sb = __float2bfloat16(s);
    g_Apad[((size_t)b * STP + PADOFF + t) * Hn + h] = sb;
    if (t == 0) {
        for (int j = 1; j < PADOFF; j++)
            g_Apad[((size_t)b * STP + j) * Hn + h] = sb;     // clip -> replicate s0
    }
}

// ---------------- Stage 2: context gate — A-resident + 4-stage B pipeline ---
// CTA: 64 t x 64 o. A = 127-row window of g_Apad, loaded ONCE (all 64 shifted
// tiles are row-offsets into it). B streamed in a 4-stage cp.async ring with
// ONE __syncthreads per chunk.
#define ROWB 272
#define ATILE (128 * ROWB)               // 34816 B (127 rows used)
#define BTILE (64 * ROWB)                // 17408 B per stage
__global__ void __launch_bounds__(256, 1)
k_ctx_mma(const float* __restrict__ b_ctx) {
    extern __shared__ char smem[];
    uint32_t sbase = s2u(smem);
    uint32_t Abuf = sbase;
    uint32_t Bbuf = sbase + ATILE;       // 4 stages of BTILE
    int tid = threadIdx.x;
    int o0 = blockIdx.x * 64, t0 = blockIdx.y * 64, b = blockIdx.z;
    int wid = tid >> 5, lane = tid & 31;
    int wr = wid >> 2, wc = wid & 3;

    const __nv_bfloat16* Asrc = g_Apad + (size_t)b * STP * Hn;

    // B loader coords: 1088 units (64 rows x 16 units of 16B); guarded strided.
    int lr[4], lc[4];
    #pragma unroll
    for (int j = 0; j < 4; j++) { int u = tid + j * 256; lr[j] = u >> 4; lc[j] = u & 15; }

    float acc[2][2][4];
    #pragma unroll
    for (int i = 0; i < 2; i++)
        #pragma unroll
        for (int j = 0; j < 2; j++)
            #pragma unroll
            for (int k = 0; k < 4; k++) acc[i][j][k] = 0.f;

    // ---- Prologue group 0: A window (127 rows: t0-63 .. t0+63) + B chunk 0
    #pragma unroll
    for (int j = 0; j < 8; j++) {
        int u = tid + j * 256;           // 0..2047; need 0..2031
        if (u < 127 * 16) {
            int r = u >> 4, c = u & 15;
            cp16(Abuf + r * ROWB + c * 16,
                 Asrc + (size_t)(PADOFF + t0 - 63 + r) * Hn + c * 8);
        }
    }
    #pragma unroll
    for (int j = 0; j < 4; j++)
        cp16(Bbuf + 0 * BTILE + lr[j] * ROWB + lc[j] * 16,
             g_Bw + ((size_t)0 * 128 + o0 + lr[j]) * 128 + lc[j] * 8);
    asm volatile("cp.async.commit_group;" ::: "memory");
    // groups 1,2: B chunks 1,2
    #pragma unroll
    for (int s = 1; s <= 2; s++) {
        #pragma unroll
        for (int j = 0; j < 4; j++)
            cp16(Bbuf + s * BTILE + lr[j] * ROWB + lc[j] * 16,
                 g_Bw + ((size_t)s * 128 + o0 + lr[j]) * 128 + lc[j] * 8);
        asm volatile("cp.async.commit_group;" ::: "memory");
    }

    uint32_t aoff = (uint32_t)((wr * 32 + (lane & 15)) * ROWB + (lane >> 4) * 16);
    uint32_t boff = (uint32_t)((wc * 16 + ((lane >> 4) & 1) * 8 + (lane & 7)) * ROWB
                               + ((lane >> 3) & 1) * 16);

    for (int kc = 0; kc < 64; kc++) {
        // ensure group for chunk kc (and A at kc=0) has landed
        int rem = 63 - kc;               // loads still outstanding beyond this chunk
        if (rem >= 3)      asm volatile("cp.async.wait_group 2;" ::: "memory");
        else if (rem == 2) asm volatile("cp.async.wait_group 2;" ::: "memory");
        else if (rem == 1) asm volatile("cp.async.wait_group 1;" ::: "memory");
        else               asm volatile("cp.async.wait_group 0;" ::: "memory");
        __syncthreads();                 // all warps done with chunk kc-1; B[kc] visible

        // prefetch chunk kc+3 into stage (kc+3)&3 (overwrites chunk kc-1's stage)
        if (kc + 3 < 64) {
            int p = kc + 3;
            uint32_t stg = Bbuf + ((uint32_t)(p & 3)) * BTILE;
            #pragma unroll
            for (int j = 0; j < 4; j++)
                cp16(stg + lr[j] * ROWB + lc[j] * 16,
                     g_Bw + ((size_t)p * 128 + o0 + lr[j]) * 128 + lc[j] * 8);
            asm volatile("cp.async.commit_group;" ::: "memory");
        }

        // compute chunk kc: A tile = rows offset (63-kc) in resident window
        uint32_t Aa = Abuf + (uint32_t)(63 - kc) * ROWB + aoff;
        uint32_t Ba = Bbuf + ((uint32_t)(kc & 3)) * BTILE + boff;
        #pragma unroll
        for (int kk = 0; kk < 8; kk++) {
            uint32_t afr[2][4], bfr[4];
            ldsm_x4(afr[0], Aa + kk * 32);
            ldsm_x4(afr[1], Aa + 16 * ROWB + kk * 32);
            ldsm_x4(bfr,    Ba + kk * 32);
            #pragma unroll
            for (int mt = 0; mt < 2; mt++)
                #pragma unroll
                for (int nt = 0; nt < 2; nt++)
                    mma16816(acc[mt][nt], afr[mt], bfr + 2 * nt);
        }
    }

    // epilogue
    int rbase = t0 + wr * 32 + (lane >> 2);
    int cbase = o0 + wc * 16 + (lane & 3) * 2;
    #pragma unroll
    for (int mt = 0; mt < 2; mt++) {
        #pragma unroll
        for (int nt = 0; nt < 2; nt++) {
            #pragma unroll
            for (int e = 0; e < 4; e++) {
                int R = rbase + mt * 16 + (e >> 1) * 8;
                int C = cbase + nt * 8 + (e & 1);
                float y = acc[mt][nt][e] + b_ctx[C];
                float gate = 1.f / (1.f + expf(-y));
                float s = g_states_bt[((size_t)b * Tn + R) * Hn + C];
                g_gated[((size_t)b * Tn + R) * Hn + C] = s * gate;
            }
        }
    }
}

// ---------------- Stage 3: probs = clip(sigmoid(gated @ W_fc^T + b_fc)) -----
__global__ void k_probs(const float* __restrict__ Wfc, const float* __restrict__ b_fc,
                        float* __restrict__ probs) {
    __shared__ float gs[64][33];
    __shared__ float wf[64][33];
    int r0 = blockIdx.x * 64;
    int tid = threadIdx.x, tx = tid & 15, ty = tid >> 4;
    float acc[4][4] = {};
    for (int k0 = 0; k0 < Hn; k0 += 32) {
        #pragma unroll
        for (int i = 0; i < 8; i++) {
            int e = tid + i * 256;
            int r = e >> 5, c = e & 31;
            gs[r][c] = g_gated[(size_t)(r0 + r) * Hn + k0 + c];
            wf[r][c] = Wfc[(size_t)r * Hn + k0 + c];
        }
        __syncthreads();
        #pragma unroll
        for (int k = 0; k < 32; k++) {
            float a[4], w[4];
            #pragma unroll
            for (int i = 0; i < 4; i++) a[i] = gs[ty * 4 + i][k];
            #pragma unroll
            for (int j = 0; j < 4; j++) w[j] = wf[tx * 4 + j][k];
            #pragma unroll
            for (int i = 0; i < 4; i++)
                #pragma unroll
                for (int j = 0; j < 4; j++) acc[i][j] += a[i] * w[j];
        }
        __syncthreads();
    }
    #pragma unroll
    for (int i = 0; i < 4; i++) {
        int row = r0 + ty * 4 + i;
        #pragma unroll
        for (int j = 0; j < 4; j++) {
            int p = tx * 4 + j;
            float y = acc[i][j] + b_fc[p];
            float pr = 1.f / (1.f + expf(-y));
            pr = fminf(fmaxf(pr, 0.001f), 0.999f);
            probs[(size_t)row * Pn + p] = pr;
        }
    }
}

// ---------------- launch -----------------------------------------------------
extern "C" void kernel_launch(void* const* d_in, const int* in_sizes, int n_in,
                              void* d_out, int out_size) {
    const float* x     = (const float*)d_in[0];
    const float* W_ih  = (const float*)d_in[1];
    // d_in[2] = W_hh (unused: hidden state is always zero in the reference)
    const float* b_ih  = (const float*)d_in[3];
    const float* b_hh  = (const float*)d_in[4];
    const float* W_ctx = (const float*)d_in[5];
    const float* b_ctx = (const float*)d_in[6];
    const float* W_fc  = (const float*)d_in[7];
    const float* b_fc  = (const float*)d_in[8];

    float* out = (float*)d_out;
    const int PROBS_N = Bn * Tn * Pn;            // 262144
    const int TOTAL_N = PROBS_N + Tn * Bn * Hn;  // 786432
    float* out_probs  = out;
    float* out_states = (out_size >= TOTAL_N) ? (out + PROBS_N) : nullptr;

    // idempotent, unconditionally each call (no static guards per harness rules)
    cudaFuncSetAttribute(k_ctx_mma, cudaFuncAttributeMaxDynamicSharedMemorySize,
                         ATILE + 4 * BTILE);
    cudaFuncSetAttribute(k_gemm_gi, cudaFuncAttributeMaxDynamicSharedMemorySize, 8 * GTILE);

    k_prep<<<128 + Bn * Tn + G3, 256>>>(W_ctx, x, W_ih);
    k_gemm_gi<<<dim3(G3 / 64, (Bn * Tn) / 64), 256, 8 * GTILE>>>(nullptr);
    k_gates<<<Bn * Tn, Hn>>>(b_ih, b_hh, out_states);
    k_ctx_mma<<<dim3(2, Tn / 64, Bn), 256, ATILE + 4 * BTILE>>>(b_ctx);
    k_probs<<<(Bn * Tn) / 64, 256>>>(W_fc, b_fc, out_probs);
}